// round 7
// baseline (speedup 1.0000x reference)
#include <cuda_runtime.h>
#include <cuda_bf16.h>
#include <math.h>
#include <stdint.h>

// GCNII forward on GB300 (base-ISA path): bf16 hi/lo split warp-HMMA GEMMs + CSR spmm.
// tcgen05 is unavailable (harness PTX targets compute_103, not 103a), so GEMMs use
// mma.sync.aligned.m16n8k16.row.col.f32.bf16.bf16.f32 (sm_80+ portable).
#define NNODES 50000
#define NEDGES 800000
#define DIN 512
#define DH 128
#define DC 40
#define NLAYERS 8
#define NSCANB 49

// ---------------- device scratch ----------------
__device__ __align__(16) float g_x   [NNODES * DH];
__device__ __align__(16) float g_h0  [NNODES * DH];
__device__ __align__(16) float g_sup [NNODES * DH];
__device__ int   g_rowstart[NNODES + 1];
__device__ int   g_cursor  [NNODES];
__device__ int   g_col     [NEDGES];
__device__ float g_wval    [NEDGES];
__device__ int   g_blocksum[64];
// B operand images, plain [n][k] bf16 hi/lo.
__device__ __align__(16) __nv_bfloat16 g_b0_hi[128 * 512];
__device__ __align__(16) __nv_bfloat16 g_b0_lo[128 * 512];
__device__ __align__(16) __nv_bfloat16 g_bl_hi[NLAYERS * 128 * 128];
__device__ __align__(16) __nv_bfloat16 g_bl_lo[NLAYERS * 128 * 128];

struct Betas { float b[NLAYERS]; };

// ---------------- PTX helpers ----------------
__device__ __forceinline__ uint32_t smem_u32(const void* p) {
    uint32_t a;
    asm("{ .reg .u64 t; cvta.to.shared.u64 t, %1; cvt.u32.u64 %0, t; }" : "=r"(a) : "l"(p));
    return a;
}
__device__ __forceinline__ void ldm_x4(uint32_t* r, uint32_t addr) {
    asm volatile("ldmatrix.sync.aligned.m8n8.x4.shared.b16 {%0,%1,%2,%3}, [%4];"
                 : "=r"(r[0]), "=r"(r[1]), "=r"(r[2]), "=r"(r[3]) : "r"(addr));
}
__device__ __forceinline__ void mma_bf16(float* c, const uint32_t* a, const uint32_t* b) {
    asm volatile("mma.sync.aligned.m16n8k16.row.col.f32.bf16.bf16.f32 "
                 "{%0,%1,%2,%3}, {%4,%5,%6,%7}, {%8,%9}, {%0,%1,%2,%3};"
                 : "+f"(c[0]), "+f"(c[1]), "+f"(c[2]), "+f"(c[3])
                 : "r"(a[0]), "r"(a[1]), "r"(a[2]), "r"(a[3]), "r"(b[0]), "r"(b[1]));
}

// ---------------- CSR build ----------------
__global__ void k_zero() {
    int i = blockIdx.x * blockDim.x + threadIdx.x;
    if (i < NNODES) g_cursor[i] = 0;
}
__global__ void k_hist(const int* __restrict__ dst) {
    int e = blockIdx.x * blockDim.x + threadIdx.x;
    if (e < NEDGES) atomicAdd(&g_cursor[dst[e]], 1);
}
__global__ void k_blocksum() {
    __shared__ int s[1024];
    int idx = blockIdx.x * 1024 + threadIdx.x;
    s[threadIdx.x] = (idx < NNODES) ? g_cursor[idx] : 0;
    __syncthreads();
    for (int off = 512; off > 0; off >>= 1) {
        if (threadIdx.x < off) s[threadIdx.x] += s[threadIdx.x + off];
        __syncthreads();
    }
    if (threadIdx.x == 0) g_blocksum[blockIdx.x] = s[0];
}
__global__ void k_scan_small() {
    int run = 0;
    for (int b = 0; b < NSCANB; b++) { int t = g_blocksum[b]; g_blocksum[b] = run; run += t; }
    g_rowstart[NNODES] = run;
}
__global__ void k_scan_final() {
    __shared__ int s[1024];
    int tid = threadIdx.x;
    int idx = blockIdx.x * 1024 + tid;
    int v = (idx < NNODES) ? g_cursor[idx] : 0;
    s[tid] = v;
    __syncthreads();
    for (int off = 1; off < 1024; off <<= 1) {
        int t = (tid >= off) ? s[tid - off] : 0;
        __syncthreads();
        s[tid] += t;
        __syncthreads();
    }
    int excl = ((tid > 0) ? s[tid - 1] : 0) + g_blocksum[blockIdx.x];
    if (idx < NNODES) { g_rowstart[idx] = excl; g_cursor[idx] = excl; }
}
__global__ void k_fill(const int* __restrict__ src, const int* __restrict__ dst,
                       const float* __restrict__ w) {
    int e = blockIdx.x * blockDim.x + threadIdx.x;
    if (e < NEDGES) {
        int d = dst[e];
        int pos = atomicAdd(&g_cursor[d], 1);
        g_col[pos]  = src[e];
        g_wval[pos] = w[e];
    }
}

// ---------------- B image prep (plain [n][k] bf16 hi/lo) ----------------
__global__ void k_prep_b0(const float* __restrict__ w_fc0) {
    int idx = blockIdx.x * blockDim.x + threadIdx.x;   // 128*512
    if (idx >= 128 * 512) return;
    int n = idx >> 9, k = idx & 511;
    float v = w_fc0[k * 128 + n];
    __nv_bfloat16 hi = __float2bfloat16(v);
    __nv_bfloat16 lo = __float2bfloat16(v - __bfloat162float(hi));
    g_b0_hi[n * 512 + k] = hi;
    g_b0_lo[n * 512 + k] = lo;
}
__global__ void k_prep_bl(const float* __restrict__ conv_w, Betas bb) {
    int idx = blockIdx.x * blockDim.x + threadIdx.x;   // 8*16384
    if (idx >= NLAYERS * 16384) return;
    int l = idx >> 14;
    int rem = idx & 16383;
    int n = rem >> 7, k = rem & 127;
    float beta = bb.b[l];
    float v = beta * conv_w[l * 16384 + k * 128 + n];
    if (k == n) v += 1.0f - beta;
    __nv_bfloat16 hi = __float2bfloat16(v);
    __nv_bfloat16 lo = __float2bfloat16(v - __bfloat162float(hi));
    g_bl_hi[l * 16384 + n * 128 + k] = hi;
    g_bl_lo[l * 16384 + n * 128 + k] = lo;
}

// ---------------- spmm: sup = 0.9 * (A_hat x) + 0.1 * h0 ----------------
__global__ __launch_bounds__(256) void k_spmm() {
    int gw = (blockIdx.x * blockDim.x + threadIdx.x) >> 5;
    int lane = threadIdx.x & 31;
    if (gw >= NNODES) return;
    int s = g_rowstart[gw];
    int e = g_rowstart[gw + 1];
    float4 acc = make_float4(0.f, 0.f, 0.f, 0.f);
    for (int base = s; base < e; base += 32) {
        int i = base + lane;
        int   c = (i < e) ? g_col[i]  : 0;
        float w = (i < e) ? g_wval[i] : 0.f;
        int cnt = min(32, e - base);
        for (int j = 0; j < cnt; j++) {
            int   cj = __shfl_sync(0xffffffffu, c, j);
            float wj = __shfl_sync(0xffffffffu, w, j);
            float4 xv = *reinterpret_cast<const float4*>(g_x + (size_t)cj * DH + lane * 4);
            acc.x += wj * xv.x; acc.y += wj * xv.y;
            acc.z += wj * xv.z; acc.w += wj * xv.w;
        }
    }
    float4 h = *reinterpret_cast<const float4*>(g_h0 + (size_t)gw * DH + lane * 4);
    float4 o;
    o.x = 0.9f * acc.x + 0.1f * h.x;
    o.y = 0.9f * acc.y + 0.1f * h.y;
    o.z = 0.9f * acc.z + 0.1f * h.z;
    o.w = 0.9f * acc.w + 0.1f * h.w;
    *reinterpret_cast<float4*>(g_sup + (size_t)gw * DH + lane * 4) = o;
}

// ---------------- HMMA GEMM: out = relu(A @ B^T [+ bias]) ----------------
// A fp32 row-major [NNODES, KTOT], B image [128 n][KTOT k] bf16 hi/lo.
// 3-pass split: D = Ahi@Bhi + Ahi@Blo + Alo@Bhi, fp32 register accumulators.
// CTA: 128x128 tile, 8 warps = 4m x 2n, warp tile 32x64.
// K chunked by 32 through static smem ([128][40] halves, padded stride).
#define KC 32
#define APAD 40

template <int KTOT, int MODE>
__global__ __launch_bounds__(256) void k_mma(const float* __restrict__ Asrc,
                                             const float* __restrict__ bias,
                                             int layer) {
    __shared__ __nv_bfloat16 sAh[128 * APAD];
    __shared__ __nv_bfloat16 sAl[128 * APAD];
    __shared__ __nv_bfloat16 sBh[128 * APAD];
    __shared__ __nv_bfloat16 sBl[128 * APAD];

    int tid = threadIdx.x, wid = tid >> 5, lane = tid & 31;
    int warp_m = wid & 3;           // 4 groups of 32 rows
    int warp_n = wid >> 2;          // 2 groups of 64 cols
    int row0 = blockIdx.x * 128;

    const float* A = (MODE == 1) ? g_sup : Asrc;
    const __nv_bfloat16* Bhi = (MODE == 1) ? (g_bl_hi + layer * 16384) : g_b0_hi;
    const __nv_bfloat16* Blo = (MODE == 1) ? (g_bl_lo + layer * 16384) : g_b0_lo;

    float acc[2][8][4];
#pragma unroll
    for (int i = 0; i < 2; i++)
#pragma unroll
        for (int j = 0; j < 8; j++)
#pragma unroll
            for (int q = 0; q < 4; q++) acc[i][j][q] = 0.f;

    // ldmatrix per-lane smem addresses (row pattern fixed; k-offset added per step)
    // A: m = mbase + (lane&15), k = (lane>>4)*8
    // B: n = nbase + (lane>>4)*8 + (lane&7), k = ((lane>>3)&1)*8
    uint32_t a_base[2], b_base[4];
#pragma unroll
    for (int mf = 0; mf < 2; mf++) {
        int m = warp_m * 32 + mf * 16 + (lane & 15);
        a_base[mf] = m * APAD + (lane >> 4) * 8;
    }
#pragma unroll
    for (int bp = 0; bp < 4; bp++) {
        int n = warp_n * 64 + bp * 16 + ((lane >> 4) * 8) + (lane & 7);
        b_base[bp] = n * APAD + (((lane >> 3) & 1) * 8);
    }
    uint32_t sAh32 = smem_u32(sAh), sAl32 = smem_u32(sAl);
    uint32_t sBh32 = smem_u32(sBh), sBl32 = smem_u32(sBl);

    const int NCHUNK = KTOT / KC;
#pragma unroll 1
    for (int c = 0; c < NCHUNK; c++) {
        // ---- stage A chunk (fp32 -> bf16 hi/lo) ----
#pragma unroll
        for (int it = 0; it < 4; it++) {
            int i = tid + it * 256;            // 0..1023
            int r = i >> 3;                    // 0..127
            int q = i & 7;                     // 0..7 (float4)
            int grow = row0 + r;
            float4 v = make_float4(0.f, 0.f, 0.f, 0.f);
            if (grow < NNODES)
                v = *reinterpret_cast<const float4*>(A + (size_t)grow * KTOT + c * KC + q * 4);
            float hx = __bfloat162float(__float2bfloat16(v.x));
            float hy = __bfloat162float(__float2bfloat16(v.y));
            float hz = __bfloat162float(__float2bfloat16(v.z));
            float hw = __bfloat162float(__float2bfloat16(v.w));
            union { __nv_bfloat162 b2[2]; uint2 u; } H, L;
            H.b2[0] = __floats2bfloat162_rn(hx, hy);
            H.b2[1] = __floats2bfloat162_rn(hz, hw);
            L.b2[0] = __floats2bfloat162_rn(v.x - hx, v.y - hy);
            L.b2[1] = __floats2bfloat162_rn(v.z - hz, v.w - hw);
            *reinterpret_cast<uint2*>(&sAh[r * APAD + q * 4]) = H.u;
            *reinterpret_cast<uint2*>(&sAl[r * APAD + q * 4]) = L.u;
        }
        // ---- stage B chunk (flat bf16 copies) ----
#pragma unroll
        for (int it = 0; it < 4; it++) {
            int i = tid + it * 256;            // 0..1023
            int n = i >> 3;
            int q = i & 7;
            *reinterpret_cast<uint2*>(&sBh[n * APAD + q * 4]) =
                *reinterpret_cast<const uint2*>(Bhi + (size_t)n * KTOT + c * KC + q * 4);
            *reinterpret_cast<uint2*>(&sBl[n * APAD + q * 4]) =
                *reinterpret_cast<const uint2*>(Blo + (size_t)n * KTOT + c * KC + q * 4);
        }
        __syncthreads();

        // ---- compute: 3 passes x 2 k-steps ----
#pragma unroll
        for (int pass = 0; pass < 3; pass++) {
            uint32_t aS = (pass == 2) ? sAl32 : sAh32;
            uint32_t bS = (pass == 1) ? sBl32 : sBh32;
#pragma unroll
            for (int ks = 0; ks < 2; ks++) {
                int k0 = ks * 16;
                uint32_t afrag[2][4];
#pragma unroll
                for (int mf = 0; mf < 2; mf++)
                    ldm_x4(afrag[mf], aS + (a_base[mf] + k0) * 2);
                uint32_t bfrag[4][4];
#pragma unroll
                for (int bp = 0; bp < 4; bp++)
                    ldm_x4(bfrag[bp], bS + (b_base[bp] + k0) * 2);
#pragma unroll
                for (int mf = 0; mf < 2; mf++)
#pragma unroll
                    for (int nf = 0; nf < 8; nf++)
                        mma_bf16(acc[mf][nf], afrag[mf], &bfrag[nf >> 1][(nf & 1) * 2]);
            }
        }
        __syncthreads();
    }

    // ---- epilogue: bias/relu, store fp32 ----
#pragma unroll
    for (int mf = 0; mf < 2; mf++) {
        int rbase = row0 + warp_m * 32 + mf * 16 + (lane >> 2);
#pragma unroll
        for (int half = 0; half < 2; half++) {
            int grow = rbase + half * 8;
            if (grow >= NNODES) continue;
#pragma unroll
            for (int nf = 0; nf < 8; nf++) {
                int ncol = warp_n * 64 + nf * 8 + (lane & 3) * 2;
                float v0 = acc[mf][nf][half * 2 + 0];
                float v1 = acc[mf][nf][half * 2 + 1];
                if (MODE == 0) { v0 += bias[ncol]; v1 += bias[ncol + 1]; }
                v0 = fmaxf(v0, 0.f);
                v1 = fmaxf(v1, 0.f);
                float2 o = make_float2(v0, v1);
                *reinterpret_cast<float2*>(g_x + (size_t)grow * DH + ncol) = o;
                if (MODE == 0)
                    *reinterpret_cast<float2*>(g_h0 + (size_t)grow * DH + ncol) = o;
            }
        }
    }
}

// ---------------- fc1: out = g_x @ W + bias ----------------
__global__ __launch_bounds__(256) void k_fc1(const float* __restrict__ W,
                                             const float* __restrict__ bias,
                                             float* __restrict__ out) {
    __shared__ float xs[32 * 132];
    __shared__ float Ws[128 * 40];
    int tid = threadIdx.x;
    int row0 = blockIdx.x * 32;

    for (int i = tid; i < 128 * 40; i += 256) Ws[i] = W[i];
#pragma unroll
    for (int it = 0; it < 4; it++) {
        int idx = tid + it * 256;
        int r = idx >> 5;
        int q = idx & 31;
        int grow = row0 + r;
        float4 v = make_float4(0.f, 0.f, 0.f, 0.f);
        if (grow < NNODES)
            v = *reinterpret_cast<const float4*>(g_x + (size_t)grow * DH + q * 4);
        xs[r * 132 + q * 4 + 0] = v.x;
        xs[r * 132 + q * 4 + 1] = v.y;
        xs[r * 132 + q * 4 + 2] = v.z;
        xs[r * 132 + q * 4 + 3] = v.w;
    }
    __syncthreads();

    int r  = tid >> 3;
    int cg = tid & 7;
    int c0 = cg * 5;
    float acc[5] = {0.f, 0.f, 0.f, 0.f, 0.f};
#pragma unroll 4
    for (int k = 0; k < 128; k++) {
        float a = xs[r * 132 + k];
#pragma unroll
        for (int j = 0; j < 5; j++) acc[j] += a * Ws[k * 40 + c0 + j];
    }
    int grow = row0 + r;
    if (grow < NNODES) {
#pragma unroll
        for (int j = 0; j < 5; j++)
            out[(size_t)grow * DC + c0 + j] = acc[j] + bias[c0 + j];
    }
}

// ---------------- host ----------------
extern "C" void kernel_launch(void* const* d_in, const int* in_sizes, int n_in,
                              void* d_out, int out_size) {
    const float* features   = (const float*)d_in[0];
    const int*   edge_index = (const int*)  d_in[1];
    const float* norm_A     = (const float*)d_in[2];
    const float* w_fc0      = (const float*)d_in[3];
    const float* b_fc0      = (const float*)d_in[4];
    const float* conv_w     = (const float*)d_in[5];
    const float* w_fc1      = (const float*)d_in[6];
    const float* b_fc1      = (const float*)d_in[7];
    float* out = (float*)d_out;

    const int* srcp = edge_index;
    const int* dstp = edge_index + NEDGES;

    // CSR build
    k_zero<<<(NNODES + 255) / 256, 256>>>();
    k_hist<<<(NEDGES + 255) / 256, 256>>>(dstp);
    k_blocksum<<<NSCANB, 1024>>>();
    k_scan_small<<<1, 1>>>();
    k_scan_final<<<NSCANB, 1024>>>();
    k_fill<<<(NEDGES + 255) / 256, 256>>>(srcp, dstp, norm_A);

    // B operand images
    Betas bb;
    for (int l = 0; l < NLAYERS; l++)
        bb.b[l] = (float)log(0.5 / (double)(l + 1) + 1.0);
    k_prep_b0<<<(128 * 512 + 255) / 256, 256>>>(w_fc0);
    k_prep_bl<<<(NLAYERS * 16384 + 255) / 256, 256>>>(conv_w, bb);

    const int GEMM_BLOCKS = (NNODES + 127) / 128;   // 391
    // fc0: x = h0 = relu(features @ w_fc0 + b)
    k_mma<DIN, 0><<<GEMM_BLOCKS, 256>>>(features, b_fc0, 0);

    // 8 GCNII layers
    const int SPMM_BLOCKS = (NNODES * 32 + 255) / 256;
    for (int l = 0; l < NLAYERS; l++) {
        k_spmm<<<SPMM_BLOCKS, 256>>>();
        k_mma<DH, 1><<<GEMM_BLOCKS, 256>>>(nullptr, nullptr, l);
    }

    // fc1
    k_fc1<<<(NNODES + 31) / 32, 256>>>(w_fc1, b_fc1, out);
}

// round 9
// speedup vs baseline: 1.0783x; 1.0783x over previous
#include <cuda_runtime.h>
#include <cuda_bf16.h>
#include <math.h>
#include <stdint.h>

// GCNII forward: round-1 structure (FFMA-efficient tiled SGEMM + CSR spmm),
// with GEMM inner product converted to packed fma.rn.f32x2 (sm_100+ base ISA,
// 2 fp32 FMA per instruction). Full fp32 precision, no split passes.
#define NNODES 50000
#define NEDGES 800000
#define DIN 512
#define DH 128
#define DC 40
#define NLAYERS 8
#define NSCANB 49

// ---------------- device scratch ----------------
__device__ __align__(16) float g_x   [NNODES * DH];
__device__ __align__(16) float g_h0  [NNODES * DH];
__device__ __align__(16) float g_sup [NNODES * DH];
__device__ __align__(16) float g_Wp  [NLAYERS * DH * DH];
__device__ int   g_rowstart[NNODES + 1];
__device__ int   g_cursor  [NNODES];
__device__ int   g_col     [NEDGES];
__device__ float g_wval    [NEDGES];
__device__ int   g_blocksum[64];

struct Betas { float b[NLAYERS]; };

// f32x2 helpers
#define FMA2(d, a, b) \
    asm("fma.rn.f32x2 %0, %1, %2, %3;" : "=l"(d) : "l"(a), "l"(b), "l"(d))
__device__ __forceinline__ unsigned long long pack_dup(float x) {
    unsigned long long r;
    uint32_t u = __float_as_uint(x);
    asm("mov.b64 %0, {%1, %1};" : "=l"(r) : "r"(u));
    return r;
}
union F2U { float2 f; unsigned long long u; };

// ---------------- CSR build ----------------
__global__ void k_zero() {
    int i = blockIdx.x * blockDim.x + threadIdx.x;
    if (i < NNODES) g_cursor[i] = 0;
}
__global__ void k_hist(const int* __restrict__ dst) {
    int e = blockIdx.x * blockDim.x + threadIdx.x;
    if (e < NEDGES) atomicAdd(&g_cursor[dst[e]], 1);
}
__global__ void k_blocksum() {
    __shared__ int s[1024];
    int idx = blockIdx.x * 1024 + threadIdx.x;
    s[threadIdx.x] = (idx < NNODES) ? g_cursor[idx] : 0;
    __syncthreads();
    for (int off = 512; off > 0; off >>= 1) {
        if (threadIdx.x < off) s[threadIdx.x] += s[threadIdx.x + off];
        __syncthreads();
    }
    if (threadIdx.x == 0) g_blocksum[blockIdx.x] = s[0];
}
__global__ void k_scan_small() {
    int run = 0;
    for (int b = 0; b < NSCANB; b++) { int t = g_blocksum[b]; g_blocksum[b] = run; run += t; }
    g_rowstart[NNODES] = run;
}
__global__ void k_scan_final() {
    __shared__ int s[1024];
    int tid = threadIdx.x;
    int idx = blockIdx.x * 1024 + tid;
    int v = (idx < NNODES) ? g_cursor[idx] : 0;
    s[tid] = v;
    __syncthreads();
    for (int off = 1; off < 1024; off <<= 1) {
        int t = (tid >= off) ? s[tid - off] : 0;
        __syncthreads();
        s[tid] += t;
        __syncthreads();
    }
    int excl = ((tid > 0) ? s[tid - 1] : 0) + g_blocksum[blockIdx.x];
    if (idx < NNODES) { g_rowstart[idx] = excl; g_cursor[idx] = excl; }
}
__global__ void k_fill(const int* __restrict__ src, const int* __restrict__ dst,
                       const float* __restrict__ w) {
    int e = blockIdx.x * blockDim.x + threadIdx.x;
    if (e < NEDGES) {
        int d = dst[e];
        int pos = atomicAdd(&g_cursor[d], 1);
        g_col[pos]  = src[e];
        g_wval[pos] = w[e];
    }
}

// ---------------- W' = beta*W + (1-beta)*I ----------------
__global__ void k_prepw(const float* __restrict__ conv_w, Betas bb) {
    int idx = blockIdx.x * blockDim.x + threadIdx.x;
    if (idx >= NLAYERS * DH * DH) return;
    int l = idx >> 14;
    int rem = idx & 16383;
    int k = rem >> 7, n = rem & 127;
    float beta = bb.b[l];
    float v = beta * conv_w[idx];
    if (k == n) v += 1.0f - beta;
    g_Wp[idx] = v;
}

// ---------------- spmm: sup = 0.9 * (A_hat x) + 0.1 * h0 ----------------
__global__ __launch_bounds__(256) void k_spmm() {
    int gw = (blockIdx.x * blockDim.x + threadIdx.x) >> 5;
    int lane = threadIdx.x & 31;
    if (gw >= NNODES) return;
    int s = g_rowstart[gw];
    int e = g_rowstart[gw + 1];
    float4 acc = make_float4(0.f, 0.f, 0.f, 0.f);
    for (int base = s; base < e; base += 32) {
        int i = base + lane;
        int   c = (i < e) ? g_col[i]  : 0;
        float w = (i < e) ? g_wval[i] : 0.f;
        int cnt = min(32, e - base);
        for (int j = 0; j < cnt; j++) {
            int   cj = __shfl_sync(0xffffffffu, c, j);
            float wj = __shfl_sync(0xffffffffu, w, j);
            float4 xv = *reinterpret_cast<const float4*>(g_x + (size_t)cj * DH + lane * 4);
            acc.x += wj * xv.x; acc.y += wj * xv.y;
            acc.z += wj * xv.z; acc.w += wj * xv.w;
        }
    }
    float4 h = *reinterpret_cast<const float4*>(g_h0 + (size_t)gw * DH + lane * 4);
    float4 o;
    o.x = 0.9f * acc.x + 0.1f * h.x;
    o.y = 0.9f * acc.y + 0.1f * h.y;
    o.z = 0.9f * acc.z + 0.1f * h.z;
    o.w = 0.9f * acc.w + 0.1f * h.w;
    *reinterpret_cast<float4*>(g_sup + (size_t)gw * DH + lane * 4) = o;
}

// ---------------- tiled SGEMM (f32x2): out = relu(A @ B [+ bias]) ----------------
// BM=128, BN=128(=H), BK=16, 256 threads, 8x8 per thread, acc packed pairwise in n.
// MODE 0: A=features, B=w_fc0, +bias, writes g_x AND g_h0.
// MODE 1: A=g_sup, B=g_Wp[layer], writes g_x.
template <int KTOT, int MODE>
__global__ __launch_bounds__(256) void k_gemm(const float* __restrict__ Ain,
                                              const float* __restrict__ Bin,
                                              const float* __restrict__ bias,
                                              int layer) {
    const int AS_LD = 132;
    __shared__ float As[16 * AS_LD];
    __shared__ float Bs[16 * 128];

    const float* A = (MODE == 1) ? g_sup : Ain;
    const float* B = (MODE == 1) ? (g_Wp + (size_t)layer * DH * DH) : Bin;

    int tid = threadIdx.x;
    int tx = tid & 15;          // n-direction: 16 threads * 8
    int ty = tid >> 4;          // m-direction: 16 threads * 8
    int row0 = blockIdx.x * 128;

    unsigned long long acc2[8][4];
#pragma unroll
    for (int i = 0; i < 8; i++)
#pragma unroll
        for (int j = 0; j < 4; j++) acc2[i][j] = 0ULL;

    for (int k0 = 0; k0 < KTOT; k0 += 16) {
        // load A tile (128 x 16), store transposed As[k][m]
#pragma unroll
        for (int it = 0; it < 2; it++) {
            int idx = tid + it * 256;      // 0..511
            int r = idx >> 2;              // 0..127
            int q = idx & 3;               // 0..3 (4 floats each)
            int grow = row0 + r;
            float4 v = make_float4(0.f, 0.f, 0.f, 0.f);
            if (grow < NNODES)
                v = *reinterpret_cast<const float4*>(A + (size_t)grow * KTOT + k0 + q * 4);
            As[(q * 4 + 0) * AS_LD + r] = v.x;
            As[(q * 4 + 1) * AS_LD + r] = v.y;
            As[(q * 4 + 2) * AS_LD + r] = v.z;
            As[(q * 4 + 3) * AS_LD + r] = v.w;
        }
        // load B tile (16 x 128)
#pragma unroll
        for (int it = 0; it < 2; it++) {
            int idx = tid + it * 256;      // 0..511
            int kk = idx >> 5;             // 0..15
            int nq = idx & 31;             // 0..31 (float4)
            *reinterpret_cast<float4*>(Bs + kk * 128 + nq * 4) =
                *reinterpret_cast<const float4*>(B + (size_t)(k0 + kk) * 128 + nq * 4);
        }
        __syncthreads();

#pragma unroll
        for (int k = 0; k < 16; k++) {
            // a: 8 floats (2x LDS.128), duplicated into b64 pairs
            float a[8];
#pragma unroll
            for (int i = 0; i < 8; i++) a[i] = As[k * AS_LD + ty * 8 + i];
            unsigned long long au[8];
#pragma unroll
            for (int i = 0; i < 8; i++) au[i] = pack_dup(a[i]);
            // b: 4 float2 pairs (LDS.64)
            unsigned long long bu[4];
#pragma unroll
            for (int j = 0; j < 4; j++) {
                F2U t;
                t.f = *reinterpret_cast<const float2*>(Bs + k * 128 + tx * 8 + j * 2);
                bu[j] = t.u;
            }
#pragma unroll
            for (int i = 0; i < 8; i++)
#pragma unroll
                for (int j = 0; j < 4; j++) FMA2(acc2[i][j], au[i], bu[j]);
        }
        __syncthreads();
    }

#pragma unroll
    for (int i = 0; i < 8; i++) {
        int grow = row0 + ty * 8 + i;
        if (grow < NNODES) {
#pragma unroll
            for (int j = 0; j < 4; j++) {
                int n = tx * 8 + j * 2;
                F2U t; t.u = acc2[i][j];
                float c0 = t.f.x, c1 = t.f.y;
                if (MODE == 0) { c0 += bias[n]; c1 += bias[n + 1]; }
                c0 = fmaxf(c0, 0.f);
                c1 = fmaxf(c1, 0.f);
                float2 o = make_float2(c0, c1);
                *reinterpret_cast<float2*>(g_x + (size_t)grow * DH + n) = o;
                if (MODE == 0)
                    *reinterpret_cast<float2*>(g_h0 + (size_t)grow * DH + n) = o;
            }
        }
    }
}

// ---------------- fc1: out = g_x @ W + bias  ([N,128]x[128,40]) ----------------
__global__ __launch_bounds__(256) void k_fc1(const float* __restrict__ W,
                                             const float* __restrict__ bias,
                                             float* __restrict__ out) {
    __shared__ float xs[32 * 132];
    __shared__ float Ws[128 * 40];
    int tid = threadIdx.x;
    int row0 = blockIdx.x * 32;

    for (int i = tid; i < 128 * 40; i += 256) Ws[i] = W[i];
#pragma unroll
    for (int it = 0; it < 4; it++) {
        int idx = tid + it * 256;
        int r = idx >> 5;
        int q = idx & 31;
        int grow = row0 + r;
        float4 v = make_float4(0.f, 0.f, 0.f, 0.f);
        if (grow < NNODES)
            v = *reinterpret_cast<const float4*>(g_x + (size_t)grow * DH + q * 4);
        xs[r * 132 + q * 4 + 0] = v.x;
        xs[r * 132 + q * 4 + 1] = v.y;
        xs[r * 132 + q * 4 + 2] = v.z;
        xs[r * 132 + q * 4 + 3] = v.w;
    }
    __syncthreads();

    int r  = tid >> 3;
    int cg = tid & 7;
    int c0 = cg * 5;
    float acc[5] = {0.f, 0.f, 0.f, 0.f, 0.f};
#pragma unroll 4
    for (int k = 0; k < 128; k++) {
        float a = xs[r * 132 + k];
#pragma unroll
        for (int j = 0; j < 5; j++) acc[j] += a * Ws[k * 40 + c0 + j];
    }
    int grow = row0 + r;
    if (grow < NNODES) {
#pragma unroll
        for (int j = 0; j < 5; j++)
            out[(size_t)grow * DC + c0 + j] = acc[j] + bias[c0 + j];
    }
}

// ---------------- host ----------------
extern "C" void kernel_launch(void* const* d_in, const int* in_sizes, int n_in,
                              void* d_out, int out_size) {
    const float* features   = (const float*)d_in[0];
    const int*   edge_index = (const int*)  d_in[1];
    const float* norm_A     = (const float*)d_in[2];
    const float* w_fc0      = (const float*)d_in[3];
    const float* b_fc0      = (const float*)d_in[4];
    const float* conv_w     = (const float*)d_in[5];
    const float* w_fc1      = (const float*)d_in[6];
    const float* b_fc1      = (const float*)d_in[7];
    float* out = (float*)d_out;

    const int* srcp = edge_index;
    const int* dstp = edge_index + NEDGES;

    // CSR build
    k_zero<<<(NNODES + 255) / 256, 256>>>();
    k_hist<<<(NEDGES + 255) / 256, 256>>>(dstp);
    k_blocksum<<<NSCANB, 1024>>>();
    k_scan_small<<<1, 1>>>();
    k_scan_final<<<NSCANB, 1024>>>();
    k_fill<<<(NEDGES + 255) / 256, 256>>>(srcp, dstp, norm_A);

    // fold identity mapping into layer weights
    Betas bb;
    for (int l = 0; l < NLAYERS; l++)
        bb.b[l] = (float)log(0.5 / (double)(l + 1) + 1.0);
    k_prepw<<<(NLAYERS * DH * DH + 255) / 256, 256>>>(conv_w, bb);

    // fc0: x = h0 = relu(features @ w_fc0 + b)
    const int GEMM_BLOCKS = (NNODES + 127) / 128;   // 391
    k_gemm<DIN, 0><<<GEMM_BLOCKS, 256>>>(features, w_fc0, b_fc0, 0);

    // 8 GCNII layers
    const int SPMM_BLOCKS = (NNODES * 32 + 255) / 256;
    for (int l = 0; l < NLAYERS; l++) {
        k_spmm<<<SPMM_BLOCKS, 256>>>();
        k_gemm<DH, 1><<<GEMM_BLOCKS, 256>>>(nullptr, nullptr, nullptr, l);
    }

    // fc1
    k_fc1<<<(NNODES + 31) / 32, 256>>>(w_fc1, b_fc1, out);
}